// round 13
// baseline (speedup 1.0000x reference)
#include <cuda_runtime.h>
#include <cstdint>

// Problem constants
#define BATCH   128
#define SEQT    2048
#define EMB     128
#define HID     256
#define G4      1024
#define VOCABN  128
#define OUTN    2

// 16 clusters x 8 CTAs; cluster owns 8 batch elems; CTA owns 32 hidden units.
// GEMM thread = (cp 0..63, kq 0..7) -> cols {2cp,2cp+1}, k in [kq*32, kq*32+32).
#define CLUSTER   8
#define BG        8
#define USLICE    32
#define NCOL      128
#define NTHREADS  512
#define KQN       8
#define KSL       32
#define SLICE_BYTES 1024  // USLICE*BG*4
#define STEP_TX     8192  // CLUSTER * SLICE_BYTES

__device__ float d_table[VOCABN * G4];

__global__ void build_table_kernel(const float* __restrict__ emb,
                                   const float* __restrict__ W_ih,
                                   const float* __restrict__ b_ih,
                                   const float* __restrict__ b_hh) {
    __shared__ float se[EMB];
    int v = blockIdx.x;
    int tid = threadIdx.x;
    if (tid < EMB) se[tid] = emb[v * EMB + tid];
    __syncthreads();
    for (int j = tid; j < G4; j += blockDim.x) {
        float acc = b_ih[j] + b_hh[j];
        const float* w = W_ih + (size_t)j * EMB;
        #pragma unroll 8
        for (int e = 0; e < EMB; e++) acc += se[e] * w[e];
        d_table[v * G4 + j] = acc;
    }
}

// ---------- PTX helpers ----------
__device__ __forceinline__ uint32_t smem_u32(const void* p) {
    uint32_t a;
    asm("{ .reg .u64 t; cvta.to.shared.u64 t, %1; cvt.u32.u64 %0, t; }"
        : "=r"(a) : "l"(p));
    return a;
}
__device__ __forceinline__ void ffma2(unsigned long long& d, unsigned long long a,
                                      unsigned long long b, unsigned long long c) {
    asm("fma.rn.f32x2 %0, %1, %2, %3;" : "=l"(d) : "l"(a), "l"(b), "l"(c));
}
__device__ __forceinline__ unsigned long long dup2(float x) {
    unsigned long long r;
    uint32_t xi = __float_as_uint(x);
    asm("mov.b64 %0, {%1, %1};" : "=l"(r) : "r"(xi));
    return r;
}
__device__ __forceinline__ void unpack2(float& x, float& y, unsigned long long v) {
    uint32_t xi, yi;
    asm("mov.b64 {%0, %1}, %2;" : "=r"(xi), "=r"(yi) : "l"(v));
    x = __uint_as_float(xi); y = __uint_as_float(yi);
}
__device__ __forceinline__ void lds_v2_u64(unsigned long long& a, unsigned long long& b,
                                           uint32_t addr) {
    asm volatile("ld.shared.v2.b64 {%0, %1}, [%2];" : "=l"(a), "=l"(b) : "r"(addr));
}
__device__ __forceinline__ void cluster_sync_ptx() {
    asm volatile("barrier.cluster.arrive.aligned;" ::: "memory");
    asm volatile("barrier.cluster.wait.aligned;" ::: "memory");
}
__device__ __forceinline__ void mbar_init(uint32_t addr, uint32_t cnt) {
    asm volatile("mbarrier.init.shared.b64 [%0], %1;" :: "r"(addr), "r"(cnt) : "memory");
}
__device__ __forceinline__ void mbar_arm(uint32_t addr, uint32_t tx) {
    asm volatile("mbarrier.arrive.expect_tx.shared.b64 _, [%0], %1;"
                 :: "r"(addr), "r"(tx) : "memory");
}
__device__ __forceinline__ void mbar_wait(uint32_t addr, uint32_t parity) {
    uint32_t done;
    asm volatile(
        "{\n\t.reg .pred p;\n\t"
        "mbarrier.try_wait.parity.acquire.cta.shared::cta.b64 p, [%1], %2;\n\t"
        "selp.b32 %0, 1, 0, p;\n\t}"
        : "=r"(done) : "r"(addr), "r"(parity) : "memory");
    if (!done) {
        asm volatile(
            "{\n\t.reg .pred P1;\n\t"
            "WAIT_LOOP_%=:\n\t"
            "mbarrier.try_wait.parity.acquire.cta.shared::cta.b64 P1, [%0], %1, 0x989680;\n\t"
            "@P1 bra.uni WAIT_DONE_%=;\n\t"
            "bra.uni WAIT_LOOP_%=;\n\t"
            "WAIT_DONE_%=:\n\t}"
            :: "r"(addr), "r"(parity) : "memory");
    }
}
__device__ __forceinline__ void bulk_s2s_cluster(uint32_t dst_local_off, uint32_t src,
                                                 uint32_t bar_local_off, uint32_t rank,
                                                 uint32_t nbytes) {
    asm volatile(
        "{\n\t.reg .b32 rd, rb;\n\t"
        "mapa.shared::cluster.u32 rd, %0, %3;\n\t"
        "mapa.shared::cluster.u32 rb, %2, %3;\n\t"
        "cp.async.bulk.shared::cluster.shared::cta.mbarrier::complete_tx::bytes "
        "[rd], [%1], %4, [rb];\n\t}"
        :: "r"(dst_local_off), "r"(src), "r"(bar_local_off), "r"(rank), "r"(nbytes)
        : "memory");
}
__device__ __forceinline__ void fence_proxy_async_cta() {
    asm volatile("fence.proxy.async.shared::cta;" ::: "memory");
}
__device__ __forceinline__ uint32_t elect_one() {
    uint32_t pred;
    asm volatile(
        "{\n\t.reg .pred p;\n\t"
        "elect.sync _|p, 0xFFFFFFFF;\n\t"
        "selp.b32 %0, 1, 0, p;\n\t}" : "=r"(pred));
    return pred;
}
__device__ __forceinline__ float tanh_fast(float x) {
    float y;
    asm("tanh.approx.f32 %0, %1;" : "=f"(y) : "f"(x));
    return y;
}
__device__ __forceinline__ float sig_fast(float x) {
    return fmaf(0.5f, tanh_fast(0.5f * x), 0.5f);
}

// Static SMEM (same as R4):
//  hb   [2][256][8]   : double-buffered hidden state [buf][k][b]    (16 KB)
//  rp   [8][8][128]   : per-kq partial preactivations [kq][b][col]  (32 KB)
//  stage[2][32][8]    : double-buffered own h-slice [u][b]          ( 2 KB)
//  bars [2]           : mbarriers guarding hb buf0/buf1 fills
__global__ void __cluster_dims__(CLUSTER, 1, 1) __launch_bounds__(NTHREADS, 1)
lstm_persistent_kernel(const int* __restrict__ x,
                       const float* __restrict__ W_hh,
                       const float* __restrict__ fc_W,
                       const float* __restrict__ fc_b,
                       float* __restrict__ out) {
    __shared__ float hb[2 * HID * BG];
    __shared__ float rp[KQN][BG * NCOL];
    __shared__ __align__(16) float stage[2][USLICE * BG];
    __shared__ __align__(8) unsigned long long bars[2];

    const int tid = threadIdx.x;
    const int wid = tid >> 5;
    uint32_t rank;
    asm("mov.u32 %0, %%cluster_ctarank;" : "=r"(rank));
    const int batch_base = (blockIdx.x / CLUSTER) * BG;

    // GEMM role: thread = (cp, kq); owns cols c0=2cp, c1=2cp+1
    const int cp = tid & 63;
    const int kq = tid >> 6;
    const int c0 = 2 * cp, c1 = 2 * cp + 1;
    const int grow0 = (c0 & 3) * HID + (int)rank * USLICE + (c0 >> 2);
    const int grow1 = (c1 & 3) * HID + (int)rank * USLICE + (c1 >> 2);

    float w0[KSL], w1[KSL];
    {
        const float4* wp0 = reinterpret_cast<const float4*>(
            W_hh + (size_t)grow0 * HID + kq * KSL);
        const float4* wp1 = reinterpret_cast<const float4*>(
            W_hh + (size_t)grow1 * HID + kq * KSL);
        #pragma unroll
        for (int i = 0; i < KSL / 4; i++) {
            float4 v0 = wp0[i], v1 = wp1[i];
            w0[4*i+0]=v0.x; w0[4*i+1]=v0.y; w0[4*i+2]=v0.z; w0[4*i+3]=v0.w;
            w1[4*i+0]=v1.x; w1[4*i+1]=v1.y; w1[4*i+2]=v1.z; w1[4*i+3]=v1.w;
        }
    }

    // Zero hidden buffers, init barriers
    for (int idx = tid; idx < 2 * HID * BG; idx += NTHREADS) hb[idx] = 0.0f;
    const uint32_t hb_u32 = smem_u32(hb);
    const uint32_t stage_u32 = smem_u32(stage);
    const uint32_t bars_u32 = smem_u32(bars);
    if (tid == 0) {
        mbar_init(bars_u32 + 0, 1);
        mbar_init(bars_u32 + 8, 1);
    }
    __syncthreads();
    cluster_sync_ptx();
    if (tid == 0) mbar_arm(bars_u32 + 8, STEP_TX);  // bar1: fills during step 0

    // Gating role: thread tid<256 owns cell (bb, uu); warp = one batch elem.
    const int bb = tid >> 5;
    const int uu = tid & 31;
    float c_reg = 0.0f;

    const int* xrow = x + (size_t)(batch_base + bb) * SEQT;
    const float* tabu = d_table + (int)rank * USLICE + uu;
    int vcur = 0;
    if (tid < HID) vcur = xrow[0];

    int ph0 = 0, ph1 = 0;

    #pragma unroll 1
    for (int t = 0; t < SEQT; t++) {
        const int p = t & 1;

        // Prefetch this step's xg (consumed post-GEMM) and next v.
        float xg0, xg1, xg2, xg3;
        if (tid < HID) {
            const float* tv = tabu + (size_t)vcur * G4;
            xg0 = tv[0 * HID];
            xg1 = tv[1 * HID];
            xg2 = tv[2 * HID];
            xg3 = tv[3 * HID];
            if (t + 1 < SEQT) vcur = xrow[t + 1];
        }

        // Wait for h(t) (buf p) delivery; t=0 reads local zeros.
        if (t > 0) {
            if (p == 0) { mbar_wait(bars_u32 + 0, ph0); ph0 ^= 1; }
            else        { mbar_wait(bars_u32 + 8, ph1); ph1 ^= 1; }
        }
        if (tid == 0) mbar_arm(bars_u32 + (uint32_t)p * 8u, STEP_TX);

        // GEMM: acc[c][b-pair] += w_c[k] * h[kq*32+k][b-pair]
        // Software-pipelined depth 2: sets A (even k) and B (odd k).
        unsigned long long a00 = 0, a01 = 0, a02 = 0, a03 = 0;
        unsigned long long a10 = 0, a11 = 0, a12 = 0, a13 = 0;
        {
            const uint32_t hbp = hb_u32 + (uint32_t)p * (HID * BG * 4)
                                        + (uint32_t)kq * (KSL * BG * 4);
            unsigned long long A0, A1, A2, A3;   // h for even k
            unsigned long long B0, B1, B2, B3;   // h for odd k
            lds_v2_u64(A0, A1, hbp + 0u);
            lds_v2_u64(A2, A3, hbp + 16u);
            lds_v2_u64(B0, B1, hbp + 32u);
            lds_v2_u64(B2, B3, hbp + 48u);
            #pragma unroll
            for (int k = 0; k < KSL; k += 2) {
                // consume set A (k), then refill A for k+2
                {
                    unsigned long long ww0 = dup2(w0[k]);
                    unsigned long long ww1 = dup2(w1[k]);
                    ffma2(a00, ww0, A0, a00);
                    ffma2(a01, ww0, A1, a01);
                    ffma2(a02, ww0, A2, a02);
                    ffma2(a03, ww0, A3, a03);
                    ffma2(a10, ww1, A0, a10);
                    ffma2(a11, ww1, A1, a11);
                    ffma2(a12, ww1, A2, a12);
                    ffma2(a13, ww1, A3, a13);
                }
                if (k + 2 < KSL) {
                    lds_v2_u64(A0, A1, hbp + (uint32_t)(k + 2) * 32u);
                    lds_v2_u64(A2, A3, hbp + (uint32_t)(k + 2) * 32u + 16u);
                }
                // consume set B (k+1), then refill B for k+3
                {
                    unsigned long long ww0 = dup2(w0[k + 1]);
                    unsigned long long ww1 = dup2(w1[k + 1]);
                    ffma2(a00, ww0, B0, a00);
                    ffma2(a01, ww0, B1, a01);
                    ffma2(a02, ww0, B2, a02);
                    ffma2(a03, ww0, B3, a03);
                    ffma2(a10, ww1, B0, a10);
                    ffma2(a11, ww1, B1, a11);
                    ffma2(a12, ww1, B2, a12);
                    ffma2(a13, ww1, B3, a13);
                }
                if (k + 3 < KSL) {
                    lds_v2_u64(B0, B1, hbp + (uint32_t)(k + 3) * 32u);
                    lds_v2_u64(B2, B3, hbp + (uint32_t)(k + 3) * 32u + 16u);
                }
            }
        }

        // Stage partials: rp[kq][b][col]  (same as R4)
        {
            float* rme = rp[kq];
            float f0, f1;
            unpack2(f0, f1, a00); rme[0*NCOL + c0] = f0; rme[1*NCOL + c0] = f1;
            unpack2(f0, f1, a01); rme[2*NCOL + c0] = f0; rme[3*NCOL + c0] = f1;
            unpack2(f0, f1, a02); rme[4*NCOL + c0] = f0; rme[5*NCOL + c0] = f1;
            unpack2(f0, f1, a03); rme[6*NCOL + c0] = f0; rme[7*NCOL + c0] = f1;
            unpack2(f0, f1, a10); rme[0*NCOL + c1] = f0; rme[1*NCOL + c1] = f1;
            unpack2(f0, f1, a11); rme[2*NCOL + c1] = f0; rme[3*NCOL + c1] = f1;
            unpack2(f0, f1, a12); rme[4*NCOL + c1] = f0; rme[5*NCOL + c1] = f1;
            unpack2(f0, f1, a13); rme[6*NCOL + c1] = f0; rme[7*NCOL + c1] = f1;
        }
        __syncthreads();

        // Gating for cell (bb, uu): conflict-free (warp = one b, uu = lane)
        if (tid < HID) {
            float si = xg0, sf = xg1, sg = xg2, so = xg3;
            #pragma unroll
            for (int q = 0; q < KQN; q++) {
                float4 v = *reinterpret_cast<const float4*>(&rp[q][bb * NCOL + uu * 4]);
                si += v.x; sf += v.y; sg += v.z; so += v.w;
            }
            float i_ = sig_fast(si);
            float f_ = sig_fast(sf);
            float gg = tanh_fast(sg);
            float o_ = sig_fast(so);
            c_reg = fmaf(f_, c_reg, i_ * gg);
            float hnew = o_ * tanh_fast(c_reg);
            stage[p][uu * BG + bb] = hnew;   // [u][b] = hb slice layout
        }
        __syncthreads();

        // Warp w (w<8) sends the full 1KB slice to rank w; elected lane.
        if (wid < CLUSTER) {
            if (elect_one()) {
                fence_proxy_async_cta();
                uint32_t src = stage_u32 + (uint32_t)p * SLICE_BYTES;
                uint32_t dst_off = hb_u32 + (uint32_t)(p ^ 1) * (HID * BG * 4)
                                          + rank * SLICE_BYTES;
                uint32_t bar_off = bars_u32 + (uint32_t)(p ^ 1) * 8u;
                bulk_s2s_cluster(dst_off, src, bar_off, (uint32_t)wid, SLICE_BYTES);
            }
        }
    }

    // h(T) lands in buf 0 (sent during step 2047); wait so no CTA exits while
    // peers' copies into its smem are in flight.
    mbar_wait(bars_u32 + 0, ph0);

    if (rank == 0 && tid < BG * OUTN) {
        int b = tid >> 1;
        int o = tid & 1;
        float acc = fc_b[o];
        #pragma unroll 8
        for (int k = 0; k < HID; k++)
            acc = fmaf(hb[k * BG + b], fc_W[o * HID + k], acc);
        out[(batch_base + b) * OUTN + o] = acc;
    }
}

extern "C" void kernel_launch(void* const* d_in, const int* in_sizes, int n_in,
                              void* d_out, int out_size) {
    (void)in_sizes; (void)n_in; (void)out_size;
    const int*   x     = (const int*)  d_in[0];
    const float* emb   = (const float*)d_in[1];
    const float* W_ih  = (const float*)d_in[2];
    const float* W_hh  = (const float*)d_in[3];
    const float* b_ih  = (const float*)d_in[4];
    const float* b_hh  = (const float*)d_in[5];
    const float* fc_W  = (const float*)d_in[6];
    const float* fc_b  = (const float*)d_in[7];
    float* out = (float*)d_out;

    build_table_kernel<<<VOCABN, 128>>>(emb, W_ih, b_ih, b_hh);
    lstm_persistent_kernel<<<BATCH / BG * CLUSTER, NTHREADS>>>(
        x, W_hh, fc_W, fc_b, out);
}

// round 14
// speedup vs baseline: 1.0088x; 1.0088x over previous
#include <cuda_runtime.h>
#include <cstdint>

// Problem constants
#define BATCH   128
#define SEQT    2048
#define EMB     128
#define HID     256
#define G4      1024
#define VOCABN  128
#define OUTN    2

// 16 clusters x 8 CTAs; cluster owns 8 batch elems; CTA owns 32 hidden units.
// GEMM thread = (cp 0..63, kq 0..7) -> cols {2cp,2cp+1}, k in [kq*32, kq*32+32).
#define CLUSTER   8
#define BG        8
#define USLICE    32
#define NCOL      128
#define NTHREADS  512
#define KQN       8
#define KSL       32
#define SLICE_BYTES 1024  // USLICE*BG*4
#define STEP_TX     8192  // CLUSTER * SLICE_BYTES

__device__ float d_table[VOCABN * G4];

__global__ void build_table_kernel(const float* __restrict__ emb,
                                   const float* __restrict__ W_ih,
                                   const float* __restrict__ b_ih,
                                   const float* __restrict__ b_hh) {
    __shared__ float se[EMB];
    int v = blockIdx.x;
    int tid = threadIdx.x;
    if (tid < EMB) se[tid] = emb[v * EMB + tid];
    __syncthreads();
    for (int j = tid; j < G4; j += blockDim.x) {
        float acc = b_ih[j] + b_hh[j];
        const float* w = W_ih + (size_t)j * EMB;
        #pragma unroll 8
        for (int e = 0; e < EMB; e++) acc += se[e] * w[e];
        d_table[v * G4 + j] = acc;
    }
}

// ---------- PTX helpers ----------
__device__ __forceinline__ uint32_t smem_u32(const void* p) {
    uint32_t a;
    asm("{ .reg .u64 t; cvta.to.shared.u64 t, %1; cvt.u32.u64 %0, t; }"
        : "=r"(a) : "l"(p));
    return a;
}
__device__ __forceinline__ void ffma2(unsigned long long& d, unsigned long long a,
                                      unsigned long long b, unsigned long long c) {
    asm("fma.rn.f32x2 %0, %1, %2, %3;" : "=l"(d) : "l"(a), "l"(b), "l"(c));
}
__device__ __forceinline__ unsigned long long dup2(float x) {
    unsigned long long r;
    uint32_t xi = __float_as_uint(x);
    asm("mov.b64 %0, {%1, %1};" : "=l"(r) : "r"(xi));
    return r;
}
__device__ __forceinline__ void unpack2(float& x, float& y, unsigned long long v) {
    uint32_t xi, yi;
    asm("mov.b64 {%0, %1}, %2;" : "=r"(xi), "=r"(yi) : "l"(v));
    x = __uint_as_float(xi); y = __uint_as_float(yi);
}
__device__ __forceinline__ void lds_v2_u64(unsigned long long& a, unsigned long long& b,
                                           uint32_t addr) {
    asm volatile("ld.shared.v2.b64 {%0, %1}, [%2];" : "=l"(a), "=l"(b) : "r"(addr));
}
__device__ __forceinline__ void cluster_sync_ptx() {
    asm volatile("barrier.cluster.arrive.aligned;" ::: "memory");
    asm volatile("barrier.cluster.wait.aligned;" ::: "memory");
}
__device__ __forceinline__ void mbar_init(uint32_t addr, uint32_t cnt) {
    asm volatile("mbarrier.init.shared.b64 [%0], %1;" :: "r"(addr), "r"(cnt) : "memory");
}
__device__ __forceinline__ void mbar_arm(uint32_t addr, uint32_t tx) {
    asm volatile("mbarrier.arrive.expect_tx.shared.b64 _, [%0], %1;"
                 :: "r"(addr), "r"(tx) : "memory");
}
__device__ __forceinline__ void mbar_wait(uint32_t addr, uint32_t parity) {
    uint32_t done;
    asm volatile(
        "{\n\t.reg .pred p;\n\t"
        "mbarrier.try_wait.parity.acquire.cta.shared::cta.b64 p, [%1], %2;\n\t"
        "selp.b32 %0, 1, 0, p;\n\t}"
        : "=r"(done) : "r"(addr), "r"(parity) : "memory");
    if (!done) {
        asm volatile(
            "{\n\t.reg .pred P1;\n\t"
            "WAIT_LOOP_%=:\n\t"
            "mbarrier.try_wait.parity.acquire.cta.shared::cta.b64 P1, [%0], %1, 0x989680;\n\t"
            "@P1 bra.uni WAIT_DONE_%=;\n\t"
            "bra.uni WAIT_LOOP_%=;\n\t"
            "WAIT_DONE_%=:\n\t}"
            :: "r"(addr), "r"(parity) : "memory");
    }
}
__device__ __forceinline__ void bulk_s2s_cluster(uint32_t dst_local_off, uint32_t src,
                                                 uint32_t bar_local_off, uint32_t rank,
                                                 uint32_t nbytes) {
    asm volatile(
        "{\n\t.reg .b32 rd, rb;\n\t"
        "mapa.shared::cluster.u32 rd, %0, %3;\n\t"
        "mapa.shared::cluster.u32 rb, %2, %3;\n\t"
        "cp.async.bulk.shared::cluster.shared::cta.mbarrier::complete_tx::bytes "
        "[rd], [%1], %4, [rb];\n\t}"
        :: "r"(dst_local_off), "r"(src), "r"(bar_local_off), "r"(rank), "r"(nbytes)
        : "memory");
}
__device__ __forceinline__ void fence_proxy_async_cta() {
    asm volatile("fence.proxy.async.shared::cta;" ::: "memory");
}
__device__ __forceinline__ uint32_t elect_one() {
    uint32_t pred;
    asm volatile(
        "{\n\t.reg .pred p;\n\t"
        "elect.sync _|p, 0xFFFFFFFF;\n\t"
        "selp.b32 %0, 1, 0, p;\n\t}" : "=r"(pred));
    return pred;
}
__device__ __forceinline__ float tanh_fast(float x) {
    float y;
    asm("tanh.approx.f32 %0, %1;" : "=f"(y) : "f"(x));
    return y;
}
__device__ __forceinline__ float sig_fast(float x) {
    return fmaf(0.5f, tanh_fast(0.5f * x), 0.5f);
}

// Static SMEM (same as R4):
//  hb   [2][256][8]   : double-buffered hidden state [buf][k][b]    (16 KB)
//  rp   [8][8][128]   : per-kq partial preactivations [kq][b][col]  (32 KB)
//  stage[2][32][8]    : double-buffered own h-slice [u][b]          ( 2 KB)
//  bars [2]           : mbarriers guarding hb buf0/buf1 fills
__global__ void __cluster_dims__(CLUSTER, 1, 1) __launch_bounds__(NTHREADS, 1)
lstm_persistent_kernel(const int* __restrict__ x,
                       const float* __restrict__ W_hh,
                       const float* __restrict__ fc_W,
                       const float* __restrict__ fc_b,
                       float* __restrict__ out) {
    __shared__ float hb[2 * HID * BG];
    __shared__ float rp[KQN][BG * NCOL];
    __shared__ __align__(16) float stage[2][USLICE * BG];
    __shared__ __align__(8) unsigned long long bars[2];

    const int tid = threadIdx.x;
    const int wid = tid >> 5;
    uint32_t rank;
    asm("mov.u32 %0, %%cluster_ctarank;" : "=r"(rank));
    const int batch_base = (blockIdx.x / CLUSTER) * BG;

    // GEMM role: thread = (cp, kq); owns cols c0=2cp, c1=2cp+1
    const int cp = tid & 63;
    const int kq = tid >> 6;
    const int c0 = 2 * cp, c1 = 2 * cp + 1;
    const int grow0 = (c0 & 3) * HID + (int)rank * USLICE + (c0 >> 2);
    const int grow1 = (c1 & 3) * HID + (int)rank * USLICE + (c1 >> 2);

    float w0[KSL], w1[KSL];
    {
        const float4* wp0 = reinterpret_cast<const float4*>(
            W_hh + (size_t)grow0 * HID + kq * KSL);
        const float4* wp1 = reinterpret_cast<const float4*>(
            W_hh + (size_t)grow1 * HID + kq * KSL);
        #pragma unroll
        for (int i = 0; i < KSL / 4; i++) {
            float4 v0 = wp0[i], v1 = wp1[i];
            w0[4*i+0]=v0.x; w0[4*i+1]=v0.y; w0[4*i+2]=v0.z; w0[4*i+3]=v0.w;
            w1[4*i+0]=v1.x; w1[4*i+1]=v1.y; w1[4*i+2]=v1.z; w1[4*i+3]=v1.w;
        }
    }

    // Zero hidden buffers, init barriers
    for (int idx = tid; idx < 2 * HID * BG; idx += NTHREADS) hb[idx] = 0.0f;
    const uint32_t hb_u32 = smem_u32(hb);
    const uint32_t stage_u32 = smem_u32(stage);
    const uint32_t bars_u32 = smem_u32(bars);
    if (tid == 0) {
        mbar_init(bars_u32 + 0, 1);
        mbar_init(bars_u32 + 8, 1);
    }
    __syncthreads();
    cluster_sync_ptx();
    if (tid == 0) mbar_arm(bars_u32 + 8, STEP_TX);  // bar1: fills during step 0

    // Gating role: thread tid<256 owns cell (bb, uu); warp = one batch elem.
    const int bb = tid >> 5;
    const int uu = tid & 31;
    float c_reg = 0.0f;

    const int* xrow = x + (size_t)(batch_base + bb) * SEQT;
    const float* tabu = d_table + (int)rank * USLICE + uu;
    int vcur = 0;
    if (tid < HID) vcur = xrow[0];

    int ph0 = 0, ph1 = 0;

    #pragma unroll 1
    for (int t = 0; t < SEQT; t++) {
        const int p = t & 1;

        // Prefetch this step's xg (consumed post-GEMM) and next v.
        float xg0, xg1, xg2, xg3;
        if (tid < HID) {
            const float* tv = tabu + (size_t)vcur * G4;
            xg0 = tv[0 * HID];
            xg1 = tv[1 * HID];
            xg2 = tv[2 * HID];
            xg3 = tv[3 * HID];
            if (t + 1 < SEQT) vcur = xrow[t + 1];
        }

        // Wait for h(t) (buf p) delivery; t=0 reads local zeros.
        if (t > 0) {
            if (p == 0) { mbar_wait(bars_u32 + 0, ph0); ph0 ^= 1; }
            else        { mbar_wait(bars_u32 + 8, ph1); ph1 ^= 1; }
        }
        if (tid == 0) mbar_arm(bars_u32 + (uint32_t)p * 8u, STEP_TX);

        // GEMM: acc[c][b-pair] += w_c[k] * h[kq*32+k][b-pair]
        // Software-pipelined depth 2: sets A (even k) and B (odd k).
        unsigned long long a00 = 0, a01 = 0, a02 = 0, a03 = 0;
        unsigned long long a10 = 0, a11 = 0, a12 = 0, a13 = 0;
        {
            const uint32_t hbp = hb_u32 + (uint32_t)p * (HID * BG * 4)
                                        + (uint32_t)kq * (KSL * BG * 4);
            unsigned long long A0, A1, A2, A3;   // h for even k
            unsigned long long B0, B1, B2, B3;   // h for odd k
            lds_v2_u64(A0, A1, hbp + 0u);
            lds_v2_u64(A2, A3, hbp + 16u);
            lds_v2_u64(B0, B1, hbp + 32u);
            lds_v2_u64(B2, B3, hbp + 48u);
            #pragma unroll
            for (int k = 0; k < KSL; k += 2) {
                // consume set A (k), then refill A for k+2
                {
                    unsigned long long ww0 = dup2(w0[k]);
                    unsigned long long ww1 = dup2(w1[k]);
                    ffma2(a00, ww0, A0, a00);
                    ffma2(a01, ww0, A1, a01);
                    ffma2(a02, ww0, A2, a02);
                    ffma2(a03, ww0, A3, a03);
                    ffma2(a10, ww1, A0, a10);
                    ffma2(a11, ww1, A1, a11);
                    ffma2(a12, ww1, A2, a12);
                    ffma2(a13, ww1, A3, a13);
                }
                if (k + 2 < KSL) {
                    lds_v2_u64(A0, A1, hbp + (uint32_t)(k + 2) * 32u);
                    lds_v2_u64(A2, A3, hbp + (uint32_t)(k + 2) * 32u + 16u);
                }
                // consume set B (k+1), then refill B for k+3
                {
                    unsigned long long ww0 = dup2(w0[k + 1]);
                    unsigned long long ww1 = dup2(w1[k + 1]);
                    ffma2(a00, ww0, B0, a00);
                    ffma2(a01, ww0, B1, a01);
                    ffma2(a02, ww0, B2, a02);
                    ffma2(a03, ww0, B3, a03);
                    ffma2(a10, ww1, B0, a10);
                    ffma2(a11, ww1, B1, a11);
                    ffma2(a12, ww1, B2, a12);
                    ffma2(a13, ww1, B3, a13);
                }
                if (k + 3 < KSL) {
                    lds_v2_u64(B0, B1, hbp + (uint32_t)(k + 3) * 32u);
                    lds_v2_u64(B2, B3, hbp + (uint32_t)(k + 3) * 32u + 16u);
                }
            }
        }

        // Stage partials: rp[kq][b][col]  (same as R4)
        {
            float* rme = rp[kq];
            float f0, f1;
            unpack2(f0, f1, a00); rme[0*NCOL + c0] = f0; rme[1*NCOL + c0] = f1;
            unpack2(f0, f1, a01); rme[2*NCOL + c0] = f0; rme[3*NCOL + c0] = f1;
            unpack2(f0, f1, a02); rme[4*NCOL + c0] = f0; rme[5*NCOL + c0] = f1;
            unpack2(f0, f1, a03); rme[6*NCOL + c0] = f0; rme[7*NCOL + c0] = f1;
            unpack2(f0, f1, a10); rme[0*NCOL + c1] = f0; rme[1*NCOL + c1] = f1;
            unpack2(f0, f1, a11); rme[2*NCOL + c1] = f0; rme[3*NCOL + c1] = f1;
            unpack2(f0, f1, a12); rme[4*NCOL + c1] = f0; rme[5*NCOL + c1] = f1;
            unpack2(f0, f1, a13); rme[6*NCOL + c1] = f0; rme[7*NCOL + c1] = f1;
        }
        __syncthreads();

        // Gating for cell (bb, uu): conflict-free (warp = one b, uu = lane)
        if (tid < HID) {
            float si = xg0, sf = xg1, sg = xg2, so = xg3;
            #pragma unroll
            for (int q = 0; q < KQN; q++) {
                float4 v = *reinterpret_cast<const float4*>(&rp[q][bb * NCOL + uu * 4]);
                si += v.x; sf += v.y; sg += v.z; so += v.w;
            }
            float i_ = sig_fast(si);
            float f_ = sig_fast(sf);
            float gg = tanh_fast(sg);
            float o_ = sig_fast(so);
            c_reg = fmaf(f_, c_reg, i_ * gg);
            float hnew = o_ * tanh_fast(c_reg);
            stage[p][uu * BG + bb] = hnew;   // [u][b] = hb slice layout
        }
        __syncthreads();

        // Warp w (w<8) sends the full 1KB slice to rank w; elected lane.
        if (wid < CLUSTER) {
            if (elect_one()) {
                fence_proxy_async_cta();
                uint32_t src = stage_u32 + (uint32_t)p * SLICE_BYTES;
                uint32_t dst_off = hb_u32 + (uint32_t)(p ^ 1) * (HID * BG * 4)
                                          + rank * SLICE_BYTES;
                uint32_t bar_off = bars_u32 + (uint32_t)(p ^ 1) * 8u;
                bulk_s2s_cluster(dst_off, src, bar_off, (uint32_t)wid, SLICE_BYTES);
            }
        }
    }

    // h(T) lands in buf 0 (sent during step 2047); wait so no CTA exits while
    // peers' copies into its smem are in flight.
    mbar_wait(bars_u32 + 0, ph0);

    if (rank == 0 && tid < BG * OUTN) {
        int b = tid >> 1;
        int o = tid & 1;
        float acc = fc_b[o];
        #pragma unroll 8
        for (int k = 0; k < HID; k++)
            acc = fmaf(hb[k * BG + b], fc_W[o * HID + k], acc);
        out[(batch_base + b) * OUTN + o] = acc;
    }
}

extern "C" void kernel_launch(void* const* d_in, const int* in_sizes, int n_in,
                              void* d_out, int out_size) {
    (void)in_sizes; (void)n_in; (void)out_size;
    const int*   x     = (const int*)  d_in[0];
    const float* emb   = (const float*)d_in[1];
    const float* W_ih  = (const float*)d_in[2];
    const float* W_hh  = (const float*)d_in[3];
    const float* b_ih  = (const float*)d_in[4];
    const float* b_hh  = (const float*)d_in[5];
    const float* fc_W  = (const float*)d_in[6];
    const float* fc_b  = (const float*)d_in[7];
    float* out = (float*)d_out;

    build_table_kernel<<<VOCABN, 128>>>(emb, W_ih, b_ih, b_hh);
    lstm_persistent_kernel<<<BATCH / BG * CLUSTER, NTHREADS>>>(
        x, W_hh, fc_W, fc_b, out);
}

// round 15
// speedup vs baseline: 1.0093x; 1.0005x over previous
#include <cuda_runtime.h>
#include <cstdint>

// Problem constants
#define BATCH   128
#define SEQT    2048
#define EMB     128
#define HID     256
#define G4      1024
#define VOCABN  128
#define OUTN    2

// 16 clusters x 8 CTAs; cluster owns 8 batch elems; CTA owns 32 hidden units.
// GEMM thread = (cp 0..63, kq 0..7) -> cols {2cp,2cp+1}, k in [kq*32, kq*32+32).
#define CLUSTER   8
#define BG        8
#define USLICE    32
#define NCOL      128
#define NTHREADS  512
#define KQN       8
#define KSL       32
#define SLICE_BYTES 1024  // USLICE*BG*4
#define STEP_TX     8192  // CLUSTER * SLICE_BYTES

__device__ float d_table[VOCABN * G4];

__global__ void build_table_kernel(const float* __restrict__ emb,
                                   const float* __restrict__ W_ih,
                                   const float* __restrict__ b_ih,
                                   const float* __restrict__ b_hh) {
    __shared__ float se[EMB];
    int v = blockIdx.x;
    int tid = threadIdx.x;
    if (tid < EMB) se[tid] = emb[v * EMB + tid];
    __syncthreads();
    for (int j = tid; j < G4; j += blockDim.x) {
        float acc = b_ih[j] + b_hh[j];
        const float* w = W_ih + (size_t)j * EMB;
        #pragma unroll 8
        for (int e = 0; e < EMB; e++) acc += se[e] * w[e];
        d_table[v * G4 + j] = acc;
    }
}

// ---------- PTX helpers ----------
__device__ __forceinline__ uint32_t smem_u32(const void* p) {
    uint32_t a;
    asm("{ .reg .u64 t; cvta.to.shared.u64 t, %1; cvt.u32.u64 %0, t; }"
        : "=r"(a) : "l"(p));
    return a;
}
__device__ __forceinline__ void ffma2(unsigned long long& d, unsigned long long a,
                                      unsigned long long b, unsigned long long c) {
    asm("fma.rn.f32x2 %0, %1, %2, %3;" : "=l"(d) : "l"(a), "l"(b), "l"(c));
}
__device__ __forceinline__ unsigned long long dup2(float x) {
    unsigned long long r;
    uint32_t xi = __float_as_uint(x);
    asm("mov.b64 %0, {%1, %1};" : "=l"(r) : "r"(xi));
    return r;
}
__device__ __forceinline__ void unpack2(float& x, float& y, unsigned long long v) {
    uint32_t xi, yi;
    asm("mov.b64 {%0, %1}, %2;" : "=r"(xi), "=r"(yi) : "l"(v));
    x = __uint_as_float(xi); y = __uint_as_float(yi);
}
__device__ __forceinline__ void lds_v2_u64(unsigned long long& a, unsigned long long& b,
                                           uint32_t addr) {
    asm volatile("ld.shared.v2.b64 {%0, %1}, [%2];" : "=l"(a), "=l"(b) : "r"(addr));
}
__device__ __forceinline__ void cluster_sync_ptx() {
    asm volatile("barrier.cluster.arrive.aligned;" ::: "memory");
    asm volatile("barrier.cluster.wait.aligned;" ::: "memory");
}
__device__ __forceinline__ void mbar_init(uint32_t addr, uint32_t cnt) {
    asm volatile("mbarrier.init.shared.b64 [%0], %1;" :: "r"(addr), "r"(cnt) : "memory");
}
__device__ __forceinline__ void mbar_arm(uint32_t addr, uint32_t tx) {
    asm volatile("mbarrier.arrive.expect_tx.shared.b64 _, [%0], %1;"
                 :: "r"(addr), "r"(tx) : "memory");
}
__device__ __forceinline__ void mbar_wait(uint32_t addr, uint32_t parity) {
    uint32_t done;
    asm volatile(
        "{\n\t.reg .pred p;\n\t"
        "mbarrier.try_wait.parity.acquire.cta.shared::cta.b64 p, [%1], %2;\n\t"
        "selp.b32 %0, 1, 0, p;\n\t}"
        : "=r"(done) : "r"(addr), "r"(parity) : "memory");
    if (!done) {
        asm volatile(
            "{\n\t.reg .pred P1;\n\t"
            "WAIT_LOOP_%=:\n\t"
            "mbarrier.try_wait.parity.acquire.cta.shared::cta.b64 P1, [%0], %1, 0x989680;\n\t"
            "@P1 bra.uni WAIT_DONE_%=;\n\t"
            "bra.uni WAIT_LOOP_%=;\n\t"
            "WAIT_DONE_%=:\n\t}"
            :: "r"(addr), "r"(parity) : "memory");
    }
}
__device__ __forceinline__ void bulk_s2s_cluster(uint32_t dst_local_off, uint32_t src,
                                                 uint32_t bar_local_off, uint32_t rank,
                                                 uint32_t nbytes) {
    asm volatile(
        "{\n\t.reg .b32 rd, rb;\n\t"
        "mapa.shared::cluster.u32 rd, %0, %3;\n\t"
        "mapa.shared::cluster.u32 rb, %2, %3;\n\t"
        "cp.async.bulk.shared::cluster.shared::cta.mbarrier::complete_tx::bytes "
        "[rd], [%1], %4, [rb];\n\t}"
        :: "r"(dst_local_off), "r"(src), "r"(bar_local_off), "r"(rank), "r"(nbytes)
        : "memory");
}
__device__ __forceinline__ void fence_proxy_async_cta() {
    asm volatile("fence.proxy.async.shared::cta;" ::: "memory");
}
__device__ __forceinline__ uint32_t elect_one() {
    uint32_t pred;
    asm volatile(
        "{\n\t.reg .pred p;\n\t"
        "elect.sync _|p, 0xFFFFFFFF;\n\t"
        "selp.b32 %0, 1, 0, p;\n\t}" : "=r"(pred));
    return pred;
}
__device__ __forceinline__ float tanh_fast(float x) {
    float y;
    asm("tanh.approx.f32 %0, %1;" : "=f"(y) : "f"(x));
    return y;
}
__device__ __forceinline__ float sig_fast(float x) {
    return fmaf(0.5f, tanh_fast(0.5f * x), 0.5f);
}

// Static SMEM (same as R4):
//  hb   [2][256][8]   : double-buffered hidden state [buf][k][b]    (16 KB)
//  rp   [8][8][128]   : per-kq partial preactivations [kq][b][col]  (32 KB)
//  stage[2][32][8]    : double-buffered own h-slice [u][b]          ( 2 KB)
//  bars [2]           : mbarriers guarding hb buf0/buf1 fills
__global__ void __cluster_dims__(CLUSTER, 1, 1) __launch_bounds__(NTHREADS, 1)
lstm_persistent_kernel(const int* __restrict__ x,
                       const float* __restrict__ W_hh,
                       const float* __restrict__ fc_W,
                       const float* __restrict__ fc_b,
                       float* __restrict__ out) {
    __shared__ float hb[2 * HID * BG];
    __shared__ float rp[KQN][BG * NCOL];
    __shared__ __align__(16) float stage[2][USLICE * BG];
    __shared__ __align__(8) unsigned long long bars[2];

    const int tid = threadIdx.x;
    const int wid = tid >> 5;
    uint32_t rank;
    asm("mov.u32 %0, %%cluster_ctarank;" : "=r"(rank));
    const int batch_base = (blockIdx.x / CLUSTER) * BG;

    // GEMM role: thread = (cp, kq); owns cols c0=2cp, c1=2cp+1
    const int cp = tid & 63;
    const int kq = tid >> 6;
    const int c0 = 2 * cp, c1 = 2 * cp + 1;
    const int grow0 = (c0 & 3) * HID + (int)rank * USLICE + (c0 >> 2);
    const int grow1 = (c1 & 3) * HID + (int)rank * USLICE + (c1 >> 2);

    float w0[KSL], w1[KSL];
    {
        const float4* wp0 = reinterpret_cast<const float4*>(
            W_hh + (size_t)grow0 * HID + kq * KSL);
        const float4* wp1 = reinterpret_cast<const float4*>(
            W_hh + (size_t)grow1 * HID + kq * KSL);
        #pragma unroll
        for (int i = 0; i < KSL / 4; i++) {
            float4 v0 = wp0[i], v1 = wp1[i];
            w0[4*i+0]=v0.x; w0[4*i+1]=v0.y; w0[4*i+2]=v0.z; w0[4*i+3]=v0.w;
            w1[4*i+0]=v1.x; w1[4*i+1]=v1.y; w1[4*i+2]=v1.z; w1[4*i+3]=v1.w;
        }
    }

    // Zero hidden buffers, init barriers
    for (int idx = tid; idx < 2 * HID * BG; idx += NTHREADS) hb[idx] = 0.0f;
    const uint32_t hb_u32 = smem_u32(hb);
    const uint32_t stage_u32 = smem_u32(stage);
    const uint32_t bars_u32 = smem_u32(bars);
    if (tid == 0) {
        mbar_init(bars_u32 + 0, 1);
        mbar_init(bars_u32 + 8, 1);
    }
    __syncthreads();
    cluster_sync_ptx();
    if (tid == 0) mbar_arm(bars_u32 + 8, STEP_TX);  // bar1: fills during step 0

    // Gating role: thread tid<256 owns cell (bb, uu); warp = one batch elem.
    const int bb = tid >> 5;
    const int uu = tid & 31;
    float c_reg = 0.0f;

    const int* xrow = x + (size_t)(batch_base + bb) * SEQT;
    const float* tabu = d_table + (int)rank * USLICE + uu;
    int vcur = 0;
    if (tid < HID) vcur = xrow[0];

    int ph0 = 0, ph1 = 0;

    #pragma unroll 1
    for (int t = 0; t < SEQT; t++) {
        const int p = t & 1;

        // Prefetch this step's xg (consumed post-GEMM) and next v.
        float xg0, xg1, xg2, xg3;
        if (tid < HID) {
            const float* tv = tabu + (size_t)vcur * G4;
            xg0 = tv[0 * HID];
            xg1 = tv[1 * HID];
            xg2 = tv[2 * HID];
            xg3 = tv[3 * HID];
            if (t + 1 < SEQT) vcur = xrow[t + 1];
        }

        // Wait for h(t) (buf p) delivery; t=0 reads local zeros.
        if (t > 0) {
            if (p == 0) { mbar_wait(bars_u32 + 0, ph0); ph0 ^= 1; }
            else        { mbar_wait(bars_u32 + 8, ph1); ph1 ^= 1; }
        }
        if (tid == 0) mbar_arm(bars_u32 + (uint32_t)p * 8u, STEP_TX);

        // GEMM: acc[c][b-pair] += w_c[k] * h[kq*32+k][b-pair]
        // Software-pipelined depth 2: sets A (even k) and B (odd k).
        unsigned long long a00 = 0, a01 = 0, a02 = 0, a03 = 0;
        unsigned long long a10 = 0, a11 = 0, a12 = 0, a13 = 0;
        {
            const uint32_t hbp = hb_u32 + (uint32_t)p * (HID * BG * 4)
                                        + (uint32_t)kq * (KSL * BG * 4);
            unsigned long long A0, A1, A2, A3;   // h for even k
            unsigned long long B0, B1, B2, B3;   // h for odd k
            lds_v2_u64(A0, A1, hbp + 0u);
            lds_v2_u64(A2, A3, hbp + 16u);
            lds_v2_u64(B0, B1, hbp + 32u);
            lds_v2_u64(B2, B3, hbp + 48u);
            #pragma unroll
            for (int k = 0; k < KSL; k += 2) {
                // consume set A (k), then refill A for k+2
                {
                    unsigned long long ww0 = dup2(w0[k]);
                    unsigned long long ww1 = dup2(w1[k]);
                    ffma2(a00, ww0, A0, a00);
                    ffma2(a01, ww0, A1, a01);
                    ffma2(a02, ww0, A2, a02);
                    ffma2(a03, ww0, A3, a03);
                    ffma2(a10, ww1, A0, a10);
                    ffma2(a11, ww1, A1, a11);
                    ffma2(a12, ww1, A2, a12);
                    ffma2(a13, ww1, A3, a13);
                }
                if (k + 2 < KSL) {
                    lds_v2_u64(A0, A1, hbp + (uint32_t)(k + 2) * 32u);
                    lds_v2_u64(A2, A3, hbp + (uint32_t)(k + 2) * 32u + 16u);
                }
                // consume set B (k+1), then refill B for k+3
                {
                    unsigned long long ww0 = dup2(w0[k + 1]);
                    unsigned long long ww1 = dup2(w1[k + 1]);
                    ffma2(a00, ww0, B0, a00);
                    ffma2(a01, ww0, B1, a01);
                    ffma2(a02, ww0, B2, a02);
                    ffma2(a03, ww0, B3, a03);
                    ffma2(a10, ww1, B0, a10);
                    ffma2(a11, ww1, B1, a11);
                    ffma2(a12, ww1, B2, a12);
                    ffma2(a13, ww1, B3, a13);
                }
                if (k + 3 < KSL) {
                    lds_v2_u64(B0, B1, hbp + (uint32_t)(k + 3) * 32u);
                    lds_v2_u64(B2, B3, hbp + (uint32_t)(k + 3) * 32u + 16u);
                }
            }
        }

        // Stage partials: rp[kq][b][col]  (same as R4)
        {
            float* rme = rp[kq];
            float f0, f1;
            unpack2(f0, f1, a00); rme[0*NCOL + c0] = f0; rme[1*NCOL + c0] = f1;
            unpack2(f0, f1, a01); rme[2*NCOL + c0] = f0; rme[3*NCOL + c0] = f1;
            unpack2(f0, f1, a02); rme[4*NCOL + c0] = f0; rme[5*NCOL + c0] = f1;
            unpack2(f0, f1, a03); rme[6*NCOL + c0] = f0; rme[7*NCOL + c0] = f1;
            unpack2(f0, f1, a10); rme[0*NCOL + c1] = f0; rme[1*NCOL + c1] = f1;
            unpack2(f0, f1, a11); rme[2*NCOL + c1] = f0; rme[3*NCOL + c1] = f1;
            unpack2(f0, f1, a12); rme[4*NCOL + c1] = f0; rme[5*NCOL + c1] = f1;
            unpack2(f0, f1, a13); rme[6*NCOL + c1] = f0; rme[7*NCOL + c1] = f1;
        }
        __syncthreads();

        // Gating for cell (bb, uu): conflict-free (warp = one b, uu = lane)
        if (tid < HID) {
            float si = xg0, sf = xg1, sg = xg2, so = xg3;
            #pragma unroll
            for (int q = 0; q < KQN; q++) {
                float4 v = *reinterpret_cast<const float4*>(&rp[q][bb * NCOL + uu * 4]);
                si += v.x; sf += v.y; sg += v.z; so += v.w;
            }
            float i_ = sig_fast(si);
            float f_ = sig_fast(sf);
            float gg = tanh_fast(sg);
            float o_ = sig_fast(so);
            c_reg = fmaf(f_, c_reg, i_ * gg);
            float hnew = o_ * tanh_fast(c_reg);
            stage[p][uu * BG + bb] = hnew;   // [u][b] = hb slice layout
        }
        __syncthreads();

        // Warp w (w<8) sends the full 1KB slice to rank w; elected lane.
        if (wid < CLUSTER) {
            if (elect_one()) {
                fence_proxy_async_cta();
                uint32_t src = stage_u32 + (uint32_t)p * SLICE_BYTES;
                uint32_t dst_off = hb_u32 + (uint32_t)(p ^ 1) * (HID * BG * 4)
                                          + rank * SLICE_BYTES;
                uint32_t bar_off = bars_u32 + (uint32_t)(p ^ 1) * 8u;
                bulk_s2s_cluster(dst_off, src, bar_off, (uint32_t)wid, SLICE_BYTES);
            }
        }
    }

    // h(T) lands in buf 0 (sent during step 2047); wait so no CTA exits while
    // peers' copies into its smem are in flight.
    mbar_wait(bars_u32 + 0, ph0);

    if (rank == 0 && tid < BG * OUTN) {
        int b = tid >> 1;
        int o = tid & 1;
        float acc = fc_b[o];
        #pragma unroll 8
        for (int k = 0; k < HID; k++)
            acc = fmaf(hb[k * BG + b], fc_W[o * HID + k], acc);
        out[(batch_base + b) * OUTN + o] = acc;
    }
}

extern "C" void kernel_launch(void* const* d_in, const int* in_sizes, int n_in,
                              void* d_out, int out_size) {
    (void)in_sizes; (void)n_in; (void)out_size;
    const int*   x     = (const int*)  d_in[0];
    const float* emb   = (const float*)d_in[1];
    const float* W_ih  = (const float*)d_in[2];
    const float* W_hh  = (const float*)d_in[3];
    const float* b_ih  = (const float*)d_in[4];
    const float* b_hh  = (const float*)d_in[5];
    const float* fc_W  = (const float*)d_in[6];
    const float* fc_b  = (const float*)d_in[7];
    float* out = (float*)d_out;

    build_table_kernel<<<VOCABN, 128>>>(emb, W_ih, b_ih, b_hh);
    lstm_persistent_kernel<<<BATCH / BG * CLUSTER, NTHREADS>>>(
        x, W_hh, fc_W, fc_b, out);
}

// round 16
// speedup vs baseline: 1.0110x; 1.0017x over previous
#include <cuda_runtime.h>
#include <cstdint>

// Problem constants
#define BATCH   128
#define SEQT    2048
#define EMB     128
#define HID     256
#define G4      1024
#define VOCABN  128
#define OUTN    2

// 16 clusters x 8 CTAs; cluster owns 8 batch elems; CTA owns 32 hidden units.
// GEMM thread = (cp 0..63, kq 0..7) -> cols {2cp,2cp+1}, k in [kq*32, kq*32+32).
#define CLUSTER   8
#define BG        8
#define USLICE    32
#define NCOL      128
#define NTHREADS  512
#define KQN       8
#define KSL       32
#define SLICE_BYTES 1024  // USLICE*BG*4
#define STEP_TX     8192  // CLUSTER * SLICE_BYTES

__device__ float d_table[VOCABN * G4];

__global__ void build_table_kernel(const float* __restrict__ emb,
                                   const float* __restrict__ W_ih,
                                   const float* __restrict__ b_ih,
                                   const float* __restrict__ b_hh) {
    __shared__ float se[EMB];
    int v = blockIdx.x;
    int tid = threadIdx.x;
    if (tid < EMB) se[tid] = emb[v * EMB + tid];
    __syncthreads();
    for (int j = tid; j < G4; j += blockDim.x) {
        float acc = b_ih[j] + b_hh[j];
        const float* w = W_ih + (size_t)j * EMB;
        #pragma unroll 8
        for (int e = 0; e < EMB; e++) acc += se[e] * w[e];
        d_table[v * G4 + j] = acc;
    }
}

// ---------- PTX helpers ----------
__device__ __forceinline__ uint32_t smem_u32(const void* p) {
    uint32_t a;
    asm("{ .reg .u64 t; cvta.to.shared.u64 t, %1; cvt.u32.u64 %0, t; }"
        : "=r"(a) : "l"(p));
    return a;
}
__device__ __forceinline__ void ffma2(unsigned long long& d, unsigned long long a,
                                      unsigned long long b, unsigned long long c) {
    asm("fma.rn.f32x2 %0, %1, %2, %3;" : "=l"(d) : "l"(a), "l"(b), "l"(c));
}
__device__ __forceinline__ unsigned long long dup2(float x) {
    unsigned long long r;
    uint32_t xi = __float_as_uint(x);
    asm("mov.b64 %0, {%1, %1};" : "=l"(r) : "r"(xi));
    return r;
}
__device__ __forceinline__ void unpack2(float& x, float& y, unsigned long long v) {
    uint32_t xi, yi;
    asm("mov.b64 {%0, %1}, %2;" : "=r"(xi), "=r"(yi) : "l"(v));
    x = __uint_as_float(xi); y = __uint_as_float(yi);
}
__device__ __forceinline__ void lds_v2_u64(unsigned long long& a, unsigned long long& b,
                                           uint32_t addr) {
    asm volatile("ld.shared.v2.b64 {%0, %1}, [%2];" : "=l"(a), "=l"(b) : "r"(addr));
}
__device__ __forceinline__ void cluster_sync_ptx() {
    asm volatile("barrier.cluster.arrive.aligned;" ::: "memory");
    asm volatile("barrier.cluster.wait.aligned;" ::: "memory");
}
__device__ __forceinline__ void mbar_init(uint32_t addr, uint32_t cnt) {
    asm volatile("mbarrier.init.shared.b64 [%0], %1;" :: "r"(addr), "r"(cnt) : "memory");
}
__device__ __forceinline__ void mbar_arm(uint32_t addr, uint32_t tx) {
    asm volatile("mbarrier.arrive.expect_tx.shared.b64 _, [%0], %1;"
                 :: "r"(addr), "r"(tx) : "memory");
}
__device__ __forceinline__ void mbar_wait(uint32_t addr, uint32_t parity) {
    uint32_t done;
    asm volatile(
        "{\n\t.reg .pred p;\n\t"
        "mbarrier.try_wait.parity.acquire.cta.shared::cta.b64 p, [%1], %2;\n\t"
        "selp.b32 %0, 1, 0, p;\n\t}"
        : "=r"(done) : "r"(addr), "r"(parity) : "memory");
    if (!done) {
        asm volatile(
            "{\n\t.reg .pred P1;\n\t"
            "WAIT_LOOP_%=:\n\t"
            "mbarrier.try_wait.parity.acquire.cta.shared::cta.b64 P1, [%0], %1, 0x989680;\n\t"
            "@P1 bra.uni WAIT_DONE_%=;\n\t"
            "bra.uni WAIT_LOOP_%=;\n\t"
            "WAIT_DONE_%=:\n\t}"
            :: "r"(addr), "r"(parity) : "memory");
    }
}
__device__ __forceinline__ void bulk_s2s_cluster(uint32_t dst_local_off, uint32_t src,
                                                 uint32_t bar_local_off, uint32_t rank,
                                                 uint32_t nbytes) {
    asm volatile(
        "{\n\t.reg .b32 rd, rb;\n\t"
        "mapa.shared::cluster.u32 rd, %0, %3;\n\t"
        "mapa.shared::cluster.u32 rb, %2, %3;\n\t"
        "cp.async.bulk.shared::cluster.shared::cta.mbarrier::complete_tx::bytes "
        "[rd], [%1], %4, [rb];\n\t}"
        :: "r"(dst_local_off), "r"(src), "r"(bar_local_off), "r"(rank), "r"(nbytes)
        : "memory");
}
__device__ __forceinline__ void fence_proxy_async_cta() {
    asm volatile("fence.proxy.async.shared::cta;" ::: "memory");
}
__device__ __forceinline__ uint32_t elect_one() {
    uint32_t pred;
    asm volatile(
        "{\n\t.reg .pred p;\n\t"
        "elect.sync _|p, 0xFFFFFFFF;\n\t"
        "selp.b32 %0, 1, 0, p;\n\t}" : "=r"(pred));
    return pred;
}
__device__ __forceinline__ float tanh_fast(float x) {
    float y;
    asm("tanh.approx.f32 %0, %1;" : "=f"(y) : "f"(x));
    return y;
}
__device__ __forceinline__ float sig_fast(float x) {
    return fmaf(0.5f, tanh_fast(0.5f * x), 0.5f);
}

// Static SMEM (same as R4):
//  hb   [2][256][8]   : double-buffered hidden state [buf][k][b]    (16 KB)
//  rp   [8][8][128]   : per-kq partial preactivations [kq][b][col]  (32 KB)
//  stage[2][32][8]    : double-buffered own h-slice [u][b]          ( 2 KB)
//  bars [2]           : mbarriers guarding hb buf0/buf1 fills
__global__ void __cluster_dims__(CLUSTER, 1, 1) __launch_bounds__(NTHREADS, 1)
lstm_persistent_kernel(const int* __restrict__ x,
                       const float* __restrict__ W_hh,
                       const float* __restrict__ fc_W,
                       const float* __restrict__ fc_b,
                       float* __restrict__ out) {
    __shared__ float hb[2 * HID * BG];
    __shared__ float rp[KQN][BG * NCOL];
    __shared__ __align__(16) float stage[2][USLICE * BG];
    __shared__ __align__(8) unsigned long long bars[2];

    const int tid = threadIdx.x;
    const int wid = tid >> 5;
    uint32_t rank;
    asm("mov.u32 %0, %%cluster_ctarank;" : "=r"(rank));
    const int batch_base = (blockIdx.x / CLUSTER) * BG;

    // GEMM role: thread = (cp, kq); owns cols c0=2cp, c1=2cp+1
    const int cp = tid & 63;
    const int kq = tid >> 6;
    const int c0 = 2 * cp, c1 = 2 * cp + 1;
    const int grow0 = (c0 & 3) * HID + (int)rank * USLICE + (c0 >> 2);
    const int grow1 = (c1 & 3) * HID + (int)rank * USLICE + (c1 >> 2);

    float w0[KSL], w1[KSL];
    {
        const float4* wp0 = reinterpret_cast<const float4*>(
            W_hh + (size_t)grow0 * HID + kq * KSL);
        const float4* wp1 = reinterpret_cast<const float4*>(
            W_hh + (size_t)grow1 * HID + kq * KSL);
        #pragma unroll
        for (int i = 0; i < KSL / 4; i++) {
            float4 v0 = wp0[i], v1 = wp1[i];
            w0[4*i+0]=v0.x; w0[4*i+1]=v0.y; w0[4*i+2]=v0.z; w0[4*i+3]=v0.w;
            w1[4*i+0]=v1.x; w1[4*i+1]=v1.y; w1[4*i+2]=v1.z; w1[4*i+3]=v1.w;
        }
    }

    // Zero hidden buffers, init barriers
    for (int idx = tid; idx < 2 * HID * BG; idx += NTHREADS) hb[idx] = 0.0f;
    const uint32_t hb_u32 = smem_u32(hb);
    const uint32_t stage_u32 = smem_u32(stage);
    const uint32_t bars_u32 = smem_u32(bars);
    if (tid == 0) {
        mbar_init(bars_u32 + 0, 1);
        mbar_init(bars_u32 + 8, 1);
    }
    __syncthreads();
    cluster_sync_ptx();
    if (tid == 0) mbar_arm(bars_u32 + 8, STEP_TX);  // bar1: fills during step 0

    // Gating role: thread tid<256 owns cell (bb, uu); warp = one batch elem.
    const int bb = tid >> 5;
    const int uu = tid & 31;
    float c_reg = 0.0f;

    const int* xrow = x + (size_t)(batch_base + bb) * SEQT;
    const float* tabu = d_table + (int)rank * USLICE + uu;
    int vcur = 0;
    if (tid < HID) vcur = xrow[0];

    int ph0 = 0, ph1 = 0;

    #pragma unroll 1
    for (int t = 0; t < SEQT; t++) {
        const int p = t & 1;

        // Prefetch this step's xg (consumed post-GEMM) and next v.
        float xg0, xg1, xg2, xg3;
        if (tid < HID) {
            const float* tv = tabu + (size_t)vcur * G4;
            xg0 = tv[0 * HID];
            xg1 = tv[1 * HID];
            xg2 = tv[2 * HID];
            xg3 = tv[3 * HID];
            if (t + 1 < SEQT) vcur = xrow[t + 1];
        }

        // Wait for h(t) (buf p) delivery; t=0 reads local zeros.
        if (t > 0) {
            if (p == 0) { mbar_wait(bars_u32 + 0, ph0); ph0 ^= 1; }
            else        { mbar_wait(bars_u32 + 8, ph1); ph1 ^= 1; }
        }
        if (tid == 0) mbar_arm(bars_u32 + (uint32_t)p * 8u, STEP_TX);

        // GEMM: acc[c][b-pair] += w_c[k] * h[kq*32+k][b-pair]
        // Software-pipelined depth 2: sets A (even k) and B (odd k).
        unsigned long long a00 = 0, a01 = 0, a02 = 0, a03 = 0;
        unsigned long long a10 = 0, a11 = 0, a12 = 0, a13 = 0;
        {
            const uint32_t hbp = hb_u32 + (uint32_t)p * (HID * BG * 4)
                                        + (uint32_t)kq * (KSL * BG * 4);
            unsigned long long A0, A1, A2, A3;   // h for even k
            unsigned long long B0, B1, B2, B3;   // h for odd k
            lds_v2_u64(A0, A1, hbp + 0u);
            lds_v2_u64(A2, A3, hbp + 16u);
            lds_v2_u64(B0, B1, hbp + 32u);
            lds_v2_u64(B2, B3, hbp + 48u);
            #pragma unroll
            for (int k = 0; k < KSL; k += 2) {
                // consume set A (k), then refill A for k+2
                {
                    unsigned long long ww0 = dup2(w0[k]);
                    unsigned long long ww1 = dup2(w1[k]);
                    ffma2(a00, ww0, A0, a00);
                    ffma2(a01, ww0, A1, a01);
                    ffma2(a02, ww0, A2, a02);
                    ffma2(a03, ww0, A3, a03);
                    ffma2(a10, ww1, A0, a10);
                    ffma2(a11, ww1, A1, a11);
                    ffma2(a12, ww1, A2, a12);
                    ffma2(a13, ww1, A3, a13);
                }
                if (k + 2 < KSL) {
                    lds_v2_u64(A0, A1, hbp + (uint32_t)(k + 2) * 32u);
                    lds_v2_u64(A2, A3, hbp + (uint32_t)(k + 2) * 32u + 16u);
                }
                // consume set B (k+1), then refill B for k+3
                {
                    unsigned long long ww0 = dup2(w0[k + 1]);
                    unsigned long long ww1 = dup2(w1[k + 1]);
                    ffma2(a00, ww0, B0, a00);
                    ffma2(a01, ww0, B1, a01);
                    ffma2(a02, ww0, B2, a02);
                    ffma2(a03, ww0, B3, a03);
                    ffma2(a10, ww1, B0, a10);
                    ffma2(a11, ww1, B1, a11);
                    ffma2(a12, ww1, B2, a12);
                    ffma2(a13, ww1, B3, a13);
                }
                if (k + 3 < KSL) {
                    lds_v2_u64(B0, B1, hbp + (uint32_t)(k + 3) * 32u);
                    lds_v2_u64(B2, B3, hbp + (uint32_t)(k + 3) * 32u + 16u);
                }
            }
        }

        // Stage partials: rp[kq][b][col]  (same as R4)
        {
            float* rme = rp[kq];
            float f0, f1;
            unpack2(f0, f1, a00); rme[0*NCOL + c0] = f0; rme[1*NCOL + c0] = f1;
            unpack2(f0, f1, a01); rme[2*NCOL + c0] = f0; rme[3*NCOL + c0] = f1;
            unpack2(f0, f1, a02); rme[4*NCOL + c0] = f0; rme[5*NCOL + c0] = f1;
            unpack2(f0, f1, a03); rme[6*NCOL + c0] = f0; rme[7*NCOL + c0] = f1;
            unpack2(f0, f1, a10); rme[0*NCOL + c1] = f0; rme[1*NCOL + c1] = f1;
            unpack2(f0, f1, a11); rme[2*NCOL + c1] = f0; rme[3*NCOL + c1] = f1;
            unpack2(f0, f1, a12); rme[4*NCOL + c1] = f0; rme[5*NCOL + c1] = f1;
            unpack2(f0, f1, a13); rme[6*NCOL + c1] = f0; rme[7*NCOL + c1] = f1;
        }
        __syncthreads();

        // Gating for cell (bb, uu): conflict-free (warp = one b, uu = lane)
        if (tid < HID) {
            float si = xg0, sf = xg1, sg = xg2, so = xg3;
            #pragma unroll
            for (int q = 0; q < KQN; q++) {
                float4 v = *reinterpret_cast<const float4*>(&rp[q][bb * NCOL + uu * 4]);
                si += v.x; sf += v.y; sg += v.z; so += v.w;
            }
            float i_ = sig_fast(si);
            float f_ = sig_fast(sf);
            float gg = tanh_fast(sg);
            float o_ = sig_fast(so);
            c_reg = fmaf(f_, c_reg, i_ * gg);
            float hnew = o_ * tanh_fast(c_reg);
            stage[p][uu * BG + bb] = hnew;   // [u][b] = hb slice layout
        }
        __syncthreads();

        // Warp w (w<8) sends the full 1KB slice to rank w; elected lane.
        if (wid < CLUSTER) {
            if (elect_one()) {
                fence_proxy_async_cta();
                uint32_t src = stage_u32 + (uint32_t)p * SLICE_BYTES;
                uint32_t dst_off = hb_u32 + (uint32_t)(p ^ 1) * (HID * BG * 4)
                                          + rank * SLICE_BYTES;
                uint32_t bar_off = bars_u32 + (uint32_t)(p ^ 1) * 8u;
                bulk_s2s_cluster(dst_off, src, bar_off, (uint32_t)wid, SLICE_BYTES);
            }
        }
    }

    // h(T) lands in buf 0 (sent during step 2047); wait so no CTA exits while
    // peers' copies into its smem are in flight.
    mbar_wait(bars_u32 + 0, ph0);

    if (rank == 0 && tid < BG * OUTN) {
        int b = tid >> 1;
        int o = tid & 1;
        float acc = fc_b[o];
        #pragma unroll 8
        for (int k = 0; k < HID; k++)
            acc = fmaf(hb[k * BG + b], fc_W[o * HID + k], acc);
        out[(batch_base + b) * OUTN + o] = acc;
    }
}

extern "C" void kernel_launch(void* const* d_in, const int* in_sizes, int n_in,
                              void* d_out, int out_size) {
    (void)in_sizes; (void)n_in; (void)out_size;
    const int*   x     = (const int*)  d_in[0];
    const float* emb   = (const float*)d_in[1];
    const float* W_ih  = (const float*)d_in[2];
    const float* W_hh  = (const float*)d_in[3];
    const float* b_ih  = (const float*)d_in[4];
    const float* b_hh  = (const float*)d_in[5];
    const float* fc_W  = (const float*)d_in[6];
    const float* fc_b  = (const float*)d_in[7];
    float* out = (float*)d_out;

    build_table_kernel<<<VOCABN, 128>>>(emb, W_ih, b_ih, b_hh);
    lstm_persistent_kernel<<<BATCH / BG * CLUSTER, NTHREADS>>>(
        x, W_hh, fc_W, fc_b, out);
}